// round 13
// baseline (speedup 1.0000x reference)
#include <cuda_runtime.h>
#include <cstdint>

// WindowOverlapProcessor: TMA-bulk-staged gather, 1536B requests.
// Tile = (b, 8-row octet h0=8k, 64-px w slab). All 8 rows share kh=h0/8:
// window kh contributes rows 0..7 (1536B contiguous), window kh-1 rows 8..15
// (1536B contiguous). 18 chunks (2 i-rows x 9 j-windows) x 1536B staged with
// cp.async.bulk + mbarrier (bypasses the L1tex MSHR cap that pins the
// cp.async path at ~69% DRAM; 18 reqs/tile keeps the bulk engine under its
// request-rate limit, unlike R9's 66x384B). Consumer = R10 math, LDS.128
// conflict-free (chunk stride 98 f4, upper group shifted -2; all phase sets
// verified distinct mod 8). smem = 28160B exactly -> 8 blocks/SM.

#define HW_    63
#define NW_    (HW_ * HW_)
#define PLANE  (512 * 512)

// raw gaussian g[k] = exp(-(k-7.5)^2/32); normalization folded into EPS2
#define G0 0.17242162f
#define G1 0.26705262f
#define G2 0.38855860f
#define G3 0.53109700f
#define G4 0.68194030f
#define G5 0.82257760f
#define G6 0.93210250f
#define G7 0.99221790f
#define EPS2 9.1698556e-7f          // 1e-8 * s^2

__constant__ float GT[16] = { G0, G1, G2, G3, G4, G5, G6, G7,
                              G7, G6, G5, G4, G3, G2, G1, G0 };

// chunk base in float4: chunks 0..8 at k*98, chunks 9..17 at k*98-2
// (pad dropped between 8|9 and after 17) -> total 1760 f4 = 28160 B
__device__ __forceinline__ int CB(int k) { return k * 98 - (k >= 9 ? 2 : 0); }

__global__ void __launch_bounds__(128, 8)
wop_r13(const float* __restrict__ windows, float* __restrict__ out)
{
    __shared__ float4 stage[1760];            // 28160 B exactly
    // mbarrier aliased into chunk 0's pad (f4 index 96..97, never read/written
    // by TMA or consumer: TMA writes f4 0..95, consumer reads f <= 95)
    uint64_t* mbar = (uint64_t*)&stage[96];

    int tid = threadIdx.x;
    int bx  = blockIdx.x;
    int ws  = bx & 7;                  // 64-px w slab
    int oct = (bx >> 3) & 63;          // 8-row octet; kh = oct
    int b   = bx >> 9;

    int w0 = ws << 6;
    int h0 = oct << 3;
    int kh = oct;
    int jbase = (ws << 3) - 1;
    int bNW = b * NW_;

    unsigned sb = (unsigned)__cvta_generic_to_shared(stage);
    unsigned mb = (unsigned)__cvta_generic_to_shared(mbar);

    if (tid == 0)
        asm volatile("mbarrier.init.shared.b64 [%0], 1;" :: "r"(mb) : "memory");
    __syncthreads();
    if (tid == 0)
        asm volatile("mbarrier.arrive.expect_tx.shared.b64 _, [%0], %1;"
                     :: "r"(mb), "r"(27648u) : "memory");
    __syncthreads();

    // ---- staging: 18 bulk copies of 1536B ----
    if (tid < 18) {
        int ii = (tid >= 9);
        int u  = ii ? tid - 9 : tid;
        int j  = min(max(jbase + u, 0), HW_ - 1);
        int iw   = ii ? min(kh, HW_ - 1) : max(kh - 1, 0);
        int half = ii ? 0 : 1;         // kh-1 contributes its rows 8..15
        const float* src = windows + (bNW + iw * HW_ + j) * 768 + half * 384;
        unsigned dst = sb + (unsigned)(CB(tid) << 4);
        asm volatile(
            "cp.async.bulk.shared::cta.global.mbarrier::complete_tx::bytes "
            "[%0], [%1], %2, [%3];"
            :: "r"(dst), "l"(src), "r"(1536), "r"(mb) : "memory");
    }

    // ---- consumer setup (overlaps the copies) ----
    int r  = tid >> 4;                 // output row 0..7 (= window-local row)
    int wg = tid & 15;
    int w4loc = wg << 2;
    int w4 = w0 + w4loc;
    int kw = w4 >> 3;
    int u0 = wg >> 1;
    bool selhi = (wg & 1) != 0;        // dwA=12 / dwB=4 when set

    bool vi0 = (kh >= 1),  vi1 = (kh <= HW_ - 1);
    bool vj0 = (kw >= 1),  vj1 = (kw <= HW_ - 1);

    float gh0 = vi0 ? GT[r + 8] : 0.0f;   // window kh-1: dh = r+8
    float gh1 = vi1 ? GT[r]     : 0.0f;   // window kh:   dh = r

    float gwA0 = vj0 ? (selhi ? G3 : G7) : 0.0f;
    float gwA1 = vj0 ? (selhi ? G2 : G6) : 0.0f;
    float gwA2 = vj0 ? (selhi ? G1 : G5) : 0.0f;
    float gwA3 = vj0 ? (selhi ? G0 : G4) : 0.0f;
    float gwB0 = vj1 ? (selhi ? G4 : G0) : 0.0f;
    float gwB1 = vj1 ? (selhi ? G5 : G1) : 0.0f;
    float gwB2 = vj1 ? (selhi ? G6 : G2) : 0.0f;
    float gwB3 = vj1 ? (selhi ? G7 : G3) : 0.0f;

    float sh = gh0 + gh1;
    float inv0 = 1.0f / (sh * (gwA0 + gwB0) + EPS2);
    float inv1 = 1.0f / (sh * (gwA1 + gwB1) + EPS2);
    float inv2 = 1.0f / (sh * (gwA2 + gwB2) + EPS2);
    float inv3 = 1.0f / (sh * (gwA3 + gwB3) + EPS2);

    int rowoff = r * 12;
    int fA = selhi ? 9 : 6;
    int fB = selhi ? 3 : 0;
    int c00 = CB(u0)      + rowoff + fA;   // (kh-1, kw-1)
    int c01 = CB(u0 + 1)  + rowoff + fB;   // (kh-1, kw)
    int c10 = CB(9 + u0)  + rowoff + fA;   // (kh,   kw-1)
    int c11 = CB(10 + u0) + rowoff + fB;   // (kh,   kw)

    // ---- wait for staged data (acquire orders the LDS reads) ----
    {
        unsigned done;
        asm volatile(
            "{\n\t.reg .pred p;\n\t"
            "mbarrier.try_wait.parity.acquire.cta.shared::cta.b64 p, [%1], 0;\n\t"
            "selp.b32 %0, 1, 0, p;\n\t}"
            : "=r"(done) : "r"(mb) : "memory");
        if (!done) {
            asm volatile(
                "{\n\t.reg .pred P1;\n\t"
                "WL_%=:\n\t"
                "mbarrier.try_wait.parity.acquire.cta.shared::cta.b64 P1, [%0], 0, 0x989680;\n\t"
                "@P1 bra.uni WD_%=;\n\t"
                "bra.uni WL_%=;\n\t"
                "WD_%=:\n\t}"
                :: "r"(mb) : "memory");
        }
    }

    float a00, a01, a02, a10, a11, a12, a20, a21, a22, a30, a31, a32;
    // per 3-float4 group: va={p0c0,p0c1,p0c2,p1c0} vb={p1c1,p1c2,p2c0,p2c1}
    //                     vc={p2c2,p3c0,p3c1,p3c2}
    {
        float4 va = stage[c00], vb = stage[c00 + 1], vc = stage[c00 + 2];
        float q0 = gh0 * gwA0, q1 = gh0 * gwA1, q2 = gh0 * gwA2, q3 = gh0 * gwA3;
        a00 = q0 * va.x; a01 = q0 * va.y; a02 = q0 * va.z;
        a10 = q1 * va.w; a11 = q1 * vb.x; a12 = q1 * vb.y;
        a20 = q2 * vb.z; a21 = q2 * vb.w; a22 = q2 * vc.x;
        a30 = q3 * vc.y; a31 = q3 * vc.z; a32 = q3 * vc.w;
    }
    {
        float4 va = stage[c01], vb = stage[c01 + 1], vc = stage[c01 + 2];
        float q0 = gh0 * gwB0, q1 = gh0 * gwB1, q2 = gh0 * gwB2, q3 = gh0 * gwB3;
        a00 += q0 * va.x; a01 += q0 * va.y; a02 += q0 * va.z;
        a10 += q1 * va.w; a11 += q1 * vb.x; a12 += q1 * vb.y;
        a20 += q2 * vb.z; a21 += q2 * vb.w; a22 += q2 * vc.x;
        a30 += q3 * vc.y; a31 += q3 * vc.z; a32 += q3 * vc.w;
    }
    {
        float4 va = stage[c10], vb = stage[c10 + 1], vc = stage[c10 + 2];
        float q0 = gh1 * gwA0, q1 = gh1 * gwA1, q2 = gh1 * gwA2, q3 = gh1 * gwA3;
        a00 += q0 * va.x; a01 += q0 * va.y; a02 += q0 * va.z;
        a10 += q1 * va.w; a11 += q1 * vb.x; a12 += q1 * vb.y;
        a20 += q2 * vb.z; a21 += q2 * vb.w; a22 += q2 * vc.x;
        a30 += q3 * vc.y; a31 += q3 * vc.z; a32 += q3 * vc.w;
    }
    {
        float4 va = stage[c11], vb = stage[c11 + 1], vc = stage[c11 + 2];
        float q0 = gh1 * gwB0, q1 = gh1 * gwB1, q2 = gh1 * gwB2, q3 = gh1 * gwB3;
        a00 += q0 * va.x; a01 += q0 * va.y; a02 += q0 * va.z;
        a10 += q1 * va.w; a11 += q1 * vb.x; a12 += q1 * vb.y;
        a20 += q2 * vb.z; a21 += q2 * vb.w; a22 += q2 * vc.x;
        a30 += q3 * vc.y; a31 += q3 * vc.z; a32 += q3 * vc.w;
    }

    float* ob = out + b * (3 * PLANE) + ((h0 + r) << 9) + w4;
    __stcs((float4*)(ob),
           make_float4(a00 * inv0, a10 * inv1, a20 * inv2, a30 * inv3));
    __stcs((float4*)(ob + PLANE),
           make_float4(a01 * inv0, a11 * inv1, a21 * inv2, a31 * inv3));
    __stcs((float4*)(ob + 2 * PLANE),
           make_float4(a02 * inv0, a12 * inv1, a22 * inv2, a32 * inv3));
}

extern "C" void kernel_launch(void* const* d_in, const int* in_sizes, int n_in,
                              void* d_out, int out_size)
{
    const float* windows = (const float*)d_in[0];
    float* out = (float*)d_out;
    cudaFuncSetAttribute(wop_r13, cudaFuncAttributePreferredSharedMemoryCarveout, 100);
    // 8 b x 64 row-octets x 8 w-slabs = 4096 one-shot blocks
    wop_r13<<<4096, 128>>>(windows, out);
}

// round 14
// speedup vs baseline: 1.0965x; 1.0965x over previous
#include <cuda_runtime.h>

// WindowOverlapProcessor: R10 mechanics, half-size tiles for tail + interleave.
// Tile = (b, row-pair, 128-px w slab): 34 chunks x 384B (2 window rows,
// 128B-aligned) staged via cp.async, conflict-free LDS.128 (416B chunk
// stride), compile-time gaussian (normalization folded into eps').
// 64-thread blocks, 14.1KB smem -> 16 blocks/SM (32 warps): same warp count
// as R10 but 2x independent stage/compute streams and half the per-block
// duration -> half the tail-wave loss. 8192 one-shot blocks.

#define HW_      63
#define NW_      (HW_ * HW_)
#define PLANE    (512 * 512)
#define CHUNK_F4 26
#define BUF_F4   (34 * CHUNK_F4)     // 884 f4 = 14144 B

// raw (unnormalized) gaussian g[k] = exp(-(k-7.5)^2/32); s = sum
#define G0 0.17242162f
#define G1 0.26705262f
#define G2 0.38855860f
#define G3 0.53109700f
#define G4 0.68194030f
#define G5 0.82257760f
#define G6 0.93210250f
#define G7 0.99221790f
#define EPS2 9.1698556e-7f           // 1e-8 * s^2

__constant__ float GT[16] = { G0, G1, G2, G3, G4, G5, G6, G7,
                              G7, G6, G5, G4, G3, G2, G1, G0 };

__global__ void __launch_bounds__(64, 16)
wop_r14(const float* __restrict__ windows, float* __restrict__ out)
{
    __shared__ float4 stage[BUF_F4];          // 14144 B

    int tid = threadIdx.x;
    int bx  = blockIdx.x;
    int ws    = bx & 3;                // 128-px w slab
    int hpair = (bx >> 2) & 255;
    int b     = bx >> 10;
    int h0 = hpair << 1;               // even
    int w0 = ws << 7;

    int kh = h0 >> 3;
    int i0cl = max(kh - 1, 0), i1cl = min(kh, HW_ - 1);
    int dA = h0 - (i0cl << 3), dB = h0 - (i1cl << 3);   // even, [0,14]
    int jbase = (ws << 4) - 1;
    int bNW = b * NW_;

    unsigned sb = (unsigned)__cvta_generic_to_shared(stage);

    // ---- staging: 34 chunks x 24 float4 via cp.async ----
    {
        int base0 = (bNW + i0cl * HW_) * 192 + dA * 12;   // float4 units
        int base1 = (bNW + i1cl * HW_) * 192 + dB * 12;

        // i-row 0 -> chunks 0..16  (17*24 = 408 f4)
        int c = tid / 24, w = tid - c * 24;
        for (int s = tid; s < 408; s += 64) {
            int j = min(max(jbase + c, 0), HW_ - 1);
            const float4* src = ((const float4*)windows) + (base0 + j * 192 + w);
            unsigned dst = sb + (unsigned)((c * CHUNK_F4 + w) << 4);
            asm volatile("cp.async.cg.shared.global [%0], [%1], 16;"
                         :: "r"(dst), "l"(src) : "memory");
            w += 16; c += 2; if (w >= 24) { w -= 24; ++c; }
        }
        // i-row 1 -> chunks 17..33
        c = tid / 24; w = tid - c * 24;
        for (int s = tid; s < 408; s += 64) {
            int j = min(max(jbase + c, 0), HW_ - 1);
            const float4* src = ((const float4*)windows) + (base1 + j * 192 + w);
            unsigned dst = sb + (unsigned)(((17 + c) * CHUNK_F4 + w) << 4);
            asm volatile("cp.async.cg.shared.global [%0], [%1], 16;"
                         :: "r"(dst), "l"(src) : "memory");
            w += 16; c += 2; if (w >= 24) { w -= 24; ++c; }
        }
        asm volatile("cp.async.commit_group;" ::: "memory");
    }

    // ---- consumer setup (overlaps the copies) ----
    int r     = tid >> 5;              // row 0/1 (warp-uniform)
    int lane  = tid & 31;
    int w4loc = lane << 2;
    int w4 = w0 + w4loc;
    int h  = h0 + r;
    int kw = w4 >> 3;
    int u0 = lane >> 1;
    bool selhi = (lane & 1) != 0;      // dwA=12 / dwB=4 when set

    bool vi0 = (kh >= 1),  vi1 = (kh <= HW_ - 1);
    bool vj0 = (kw >= 1),  vj1 = (kw <= HW_ - 1);

    float gh0 = vi0 ? GT[(h & 7) + 8] : 0.0f;   // warp-uniform
    float gh1 = vi1 ? GT[h & 7]       : 0.0f;

    float gwA0 = vj0 ? (selhi ? G3 : G7) : 0.0f;
    float gwA1 = vj0 ? (selhi ? G2 : G6) : 0.0f;
    float gwA2 = vj0 ? (selhi ? G1 : G5) : 0.0f;
    float gwA3 = vj0 ? (selhi ? G0 : G4) : 0.0f;
    float gwB0 = vj1 ? (selhi ? G4 : G0) : 0.0f;
    float gwB1 = vj1 ? (selhi ? G5 : G1) : 0.0f;
    float gwB2 = vj1 ? (selhi ? G6 : G2) : 0.0f;
    float gwB3 = vj1 ? (selhi ? G7 : G3) : 0.0f;

    float sh = gh0 + gh1;
    float inv0 = 1.0f / (sh * (gwA0 + gwB0) + EPS2);
    float inv1 = 1.0f / (sh * (gwA1 + gwB1) + EPS2);
    float inv2 = 1.0f / (sh * (gwA2 + gwB2) + EPS2);
    float inv3 = 1.0f / (sh * (gwA3 + gwB3) + EPS2);

    int rowoff = r * 12;
    int fA = selhi ? 9 : 6;
    int fB = selhi ? 3 : 0;
    int c00 = (u0)      * CHUNK_F4 + rowoff + fA;   // (kh-1, kw-1)
    int c01 = (u0 + 1)  * CHUNK_F4 + rowoff + fB;   // (kh-1, kw)
    int c10 = (17 + u0) * CHUNK_F4 + rowoff + fA;   // (kh,   kw-1)
    int c11 = (18 + u0) * CHUNK_F4 + rowoff + fB;   // (kh,   kw)

    asm volatile("cp.async.wait_group 0;" ::: "memory");
    __syncthreads();                   // staged data visible to both warps

    float a00, a01, a02, a10, a11, a12, a20, a21, a22, a30, a31, a32;
    // per 3-float4 group: va={p0c0,p0c1,p0c2,p1c0} vb={p1c1,p1c2,p2c0,p2c1}
    //                     vc={p2c2,p3c0,p3c1,p3c2}
    {
        float4 va = stage[c00], vb = stage[c00 + 1], vc = stage[c00 + 2];
        float q0 = gh0 * gwA0, q1 = gh0 * gwA1, q2 = gh0 * gwA2, q3 = gh0 * gwA3;
        a00 = q0 * va.x; a01 = q0 * va.y; a02 = q0 * va.z;
        a10 = q1 * va.w; a11 = q1 * vb.x; a12 = q1 * vb.y;
        a20 = q2 * vb.z; a21 = q2 * vb.w; a22 = q2 * vc.x;
        a30 = q3 * vc.y; a31 = q3 * vc.z; a32 = q3 * vc.w;
    }
    {
        float4 va = stage[c01], vb = stage[c01 + 1], vc = stage[c01 + 2];
        float q0 = gh0 * gwB0, q1 = gh0 * gwB1, q2 = gh0 * gwB2, q3 = gh0 * gwB3;
        a00 += q0 * va.x; a01 += q0 * va.y; a02 += q0 * va.z;
        a10 += q1 * va.w; a11 += q1 * vb.x; a12 += q1 * vb.y;
        a20 += q2 * vb.z; a21 += q2 * vb.w; a22 += q2 * vc.x;
        a30 += q3 * vc.y; a31 += q3 * vc.z; a32 += q3 * vc.w;
    }
    {
        float4 va = stage[c10], vb = stage[c10 + 1], vc = stage[c10 + 2];
        float q0 = gh1 * gwA0, q1 = gh1 * gwA1, q2 = gh1 * gwA2, q3 = gh1 * gwA3;
        a00 += q0 * va.x; a01 += q0 * va.y; a02 += q0 * va.z;
        a10 += q1 * va.w; a11 += q1 * vb.x; a12 += q1 * vb.y;
        a20 += q2 * vb.z; a21 += q2 * vb.w; a22 += q2 * vc.x;
        a30 += q3 * vc.y; a31 += q3 * vc.z; a32 += q3 * vc.w;
    }
    {
        float4 va = stage[c11], vb = stage[c11 + 1], vc = stage[c11 + 2];
        float q0 = gh1 * gwB0, q1 = gh1 * gwB1, q2 = gh1 * gwB2, q3 = gh1 * gwB3;
        a00 += q0 * va.x; a01 += q0 * va.y; a02 += q0 * va.z;
        a10 += q1 * va.w; a11 += q1 * vb.x; a12 += q1 * vb.y;
        a20 += q2 * vb.z; a21 += q2 * vb.w; a22 += q2 * vc.x;
        a30 += q3 * vc.y; a31 += q3 * vc.z; a32 += q3 * vc.w;
    }

    float* ob = out + b * (3 * PLANE) + (h << 9) + w4;
    __stcs((float4*)(ob),
           make_float4(a00 * inv0, a10 * inv1, a20 * inv2, a30 * inv3));
    __stcs((float4*)(ob + PLANE),
           make_float4(a01 * inv0, a11 * inv1, a21 * inv2, a31 * inv3));
    __stcs((float4*)(ob + 2 * PLANE),
           make_float4(a02 * inv0, a12 * inv1, a22 * inv2, a32 * inv3));
}

extern "C" void kernel_launch(void* const* d_in, const int* in_sizes, int n_in,
                              void* d_out, int out_size)
{
    const float* windows = (const float*)d_in[0];
    float* out = (float*)d_out;
    cudaFuncSetAttribute(wop_r14, cudaFuncAttributePreferredSharedMemoryCarveout, 100);
    // 8 b x 256 h-pairs x 4 w-slabs = 8192 one-shot blocks
    wop_r14<<<8192, 64>>>(windows, out);
}

// round 15
// speedup vs baseline: 1.1099x; 1.0122x over previous
#include <cuda_runtime.h>

// WindowOverlapProcessor: 1536B-contiguous-run staging on the proven cp.async
// path. Tile = (b, 8-row octet h0=8k, 64-px w slab); all 8 rows share kh:
// window kh gives rows 0..7 (1536B contiguous), window kh-1 rows 8..15
// (1536B contiguous) -> 18 chunks x 1536B. Staged with R10-style cp.async
// loops (NOT TMA - isolates run-length from R13's TMA latency confound).
// Consumer identical to R13 (validated): chunk stride 98 f4, upper group
// shifted -2, all LDS.128 phases conflict-free. smem 28160B -> 8 blocks/SM.

#define HW_    63
#define NW_    (HW_ * HW_)
#define PLANE  (512 * 512)

// raw gaussian g[k] = exp(-(k-7.5)^2/32); normalization folded into EPS2
#define G0 0.17242162f
#define G1 0.26705262f
#define G2 0.38855860f
#define G3 0.53109700f
#define G4 0.68194030f
#define G5 0.82257760f
#define G6 0.93210250f
#define G7 0.99221790f
#define EPS2 9.1698556e-7f          // 1e-8 * s^2

__constant__ float GT[16] = { G0, G1, G2, G3, G4, G5, G6, G7,
                              G7, G6, G5, G4, G3, G2, G1, G0 };

// chunk base in float4: chunks 0..8 at k*98, chunks 9..17 at k*98-2
__device__ __forceinline__ int CB(int k) { return k * 98 - (k >= 9 ? 2 : 0); }

__global__ void __launch_bounds__(128, 8)
wop_r15(const float* __restrict__ windows, float* __restrict__ out)
{
    __shared__ float4 stage[1760];            // 28160 B

    int tid = threadIdx.x;
    int bx  = blockIdx.x;
    int ws  = bx & 7;                  // 64-px w slab
    int oct = (bx >> 3) & 63;          // 8-row octet; kh = oct
    int b   = bx >> 9;

    int w0 = ws << 6;
    int h0 = oct << 3;
    int kh = oct;
    int jbase = (ws << 3) - 1;
    int bNW = b * NW_;

    int iw0 = max(kh - 1, 0);          // contributes its rows 8..15
    int iw1 = min(kh, HW_ - 1);        // contributes its rows 0..7

    unsigned sb = (unsigned)__cvta_generic_to_shared(stage);

    // ---- staging: 18 chunks x 96 float4, cp.async, 1536B contiguous runs ----
    {
        int base0 = (bNW + iw0 * HW_) * 192 + 96;   // f4 units; rows 8..15
        int base1 = (bNW + iw1 * HW_) * 192;        // rows 0..7

        // group A: chunks 0..8 (window row kh-1)
        int c = tid / 96, w = tid - c * 96;          // c in {0,1}, w < 96
        for (int s = tid; s < 864; s += 128) {
            int j = min(max(jbase + c, 0), HW_ - 1);
            const float4* src = ((const float4*)windows) + (base0 + j * 192 + w);
            unsigned dst = sb + (unsigned)((CB(c) + w) << 4);
            asm volatile("cp.async.cg.shared.global [%0], [%1], 16;"
                         :: "r"(dst), "l"(src) : "memory");
            w += 32; c += 1; if (w >= 96) { w -= 96; ++c; }
        }
        // group B: chunks 9..17 (window row kh)
        c = tid / 96; w = tid - c * 96;
        for (int s = tid; s < 864; s += 128) {
            int j = min(max(jbase + c, 0), HW_ - 1);
            const float4* src = ((const float4*)windows) + (base1 + j * 192 + w);
            unsigned dst = sb + (unsigned)((CB(9 + c) + w) << 4);
            asm volatile("cp.async.cg.shared.global [%0], [%1], 16;"
                         :: "r"(dst), "l"(src) : "memory");
            w += 32; c += 1; if (w >= 96) { w -= 96; ++c; }
        }
        asm volatile("cp.async.commit_group;" ::: "memory");
    }

    // ---- consumer setup (overlaps the copies) ----
    int r  = tid >> 4;                 // output row 0..7 (= window-local row)
    int wg = tid & 15;
    int w4loc = wg << 2;
    int w4 = w0 + w4loc;
    int kw = w4 >> 3;
    int u0 = wg >> 1;
    bool selhi = (wg & 1) != 0;        // dwA=12 / dwB=4 when set

    bool vi0 = (kh >= 1),  vi1 = (kh <= HW_ - 1);
    bool vj0 = (kw >= 1),  vj1 = (kw <= HW_ - 1);

    float gh0 = vi0 ? GT[r + 8] : 0.0f;   // window kh-1: dh = r+8
    float gh1 = vi1 ? GT[r]     : 0.0f;   // window kh:   dh = r

    float gwA0 = vj0 ? (selhi ? G3 : G7) : 0.0f;
    float gwA1 = vj0 ? (selhi ? G2 : G6) : 0.0f;
    float gwA2 = vj0 ? (selhi ? G1 : G5) : 0.0f;
    float gwA3 = vj0 ? (selhi ? G0 : G4) : 0.0f;
    float gwB0 = vj1 ? (selhi ? G4 : G0) : 0.0f;
    float gwB1 = vj1 ? (selhi ? G5 : G1) : 0.0f;
    float gwB2 = vj1 ? (selhi ? G6 : G2) : 0.0f;
    float gwB3 = vj1 ? (selhi ? G7 : G3) : 0.0f;

    float sh = gh0 + gh1;
    float inv0 = 1.0f / (sh * (gwA0 + gwB0) + EPS2);
    float inv1 = 1.0f / (sh * (gwA1 + gwB1) + EPS2);
    float inv2 = 1.0f / (sh * (gwA2 + gwB2) + EPS2);
    float inv3 = 1.0f / (sh * (gwA3 + gwB3) + EPS2);

    int rowoff = r * 12;
    int fA = selhi ? 9 : 6;
    int fB = selhi ? 3 : 0;
    int c00 = CB(u0)      + rowoff + fA;   // (kh-1, kw-1)
    int c01 = CB(u0 + 1)  + rowoff + fB;   // (kh-1, kw)
    int c10 = CB(9 + u0)  + rowoff + fA;   // (kh,   kw-1)
    int c11 = CB(10 + u0) + rowoff + fB;   // (kh,   kw)

    asm volatile("cp.async.wait_group 0;" ::: "memory");
    __syncthreads();

    float a00, a01, a02, a10, a11, a12, a20, a21, a22, a30, a31, a32;
    // per 3-float4 group: va={p0c0,p0c1,p0c2,p1c0} vb={p1c1,p1c2,p2c0,p2c1}
    //                     vc={p2c2,p3c0,p3c1,p3c2}
    {
        float4 va = stage[c00], vb = stage[c00 + 1], vc = stage[c00 + 2];
        float q0 = gh0 * gwA0, q1 = gh0 * gwA1, q2 = gh0 * gwA2, q3 = gh0 * gwA3;
        a00 = q0 * va.x; a01 = q0 * va.y; a02 = q0 * va.z;
        a10 = q1 * va.w; a11 = q1 * vb.x; a12 = q1 * vb.y;
        a20 = q2 * vb.z; a21 = q2 * vb.w; a22 = q2 * vc.x;
        a30 = q3 * vc.y; a31 = q3 * vc.z; a32 = q3 * vc.w;
    }
    {
        float4 va = stage[c01], vb = stage[c01 + 1], vc = stage[c01 + 2];
        float q0 = gh0 * gwB0, q1 = gh0 * gwB1, q2 = gh0 * gwB2, q3 = gh0 * gwB3;
        a00 += q0 * va.x; a01 += q0 * va.y; a02 += q0 * va.z;
        a10 += q1 * va.w; a11 += q1 * vb.x; a12 += q1 * vb.y;
        a20 += q2 * vb.z; a21 += q2 * vb.w; a22 += q2 * vc.x;
        a30 += q3 * vc.y; a31 += q3 * vc.z; a32 += q3 * vc.w;
    }
    {
        float4 va = stage[c10], vb = stage[c10 + 1], vc = stage[c10 + 2];
        float q0 = gh1 * gwA0, q1 = gh1 * gwA1, q2 = gh1 * gwA2, q3 = gh1 * gwA3;
        a00 += q0 * va.x; a01 += q0 * va.y; a02 += q0 * va.z;
        a10 += q1 * va.w; a11 += q1 * vb.x; a12 += q1 * vb.y;
        a20 += q2 * vb.z; a21 += q2 * vb.w; a22 += q2 * vc.x;
        a30 += q3 * vc.y; a31 += q3 * vc.z; a32 += q3 * vc.w;
    }
    {
        float4 va = stage[c11], vb = stage[c11 + 1], vc = stage[c11 + 2];
        float q0 = gh1 * gwB0, q1 = gh1 * gwB1, q2 = gh1 * gwB2, q3 = gh1 * gwB3;
        a00 += q0 * va.x; a01 += q0 * va.y; a02 += q0 * va.z;
        a10 += q1 * va.w; a11 += q1 * vb.x; a12 += q1 * vb.y;
        a20 += q2 * vb.z; a21 += q2 * vb.w; a22 += q2 * vc.x;
        a30 += q3 * vc.y; a31 += q3 * vc.z; a32 += q3 * vc.w;
    }

    float* ob = out + b * (3 * PLANE) + ((h0 + r) << 9) + w4;
    __stcs((float4*)(ob),
           make_float4(a00 * inv0, a10 * inv1, a20 * inv2, a30 * inv3));
    __stcs((float4*)(ob + PLANE),
           make_float4(a01 * inv0, a11 * inv1, a21 * inv2, a31 * inv3));
    __stcs((float4*)(ob + 2 * PLANE),
           make_float4(a02 * inv0, a12 * inv1, a22 * inv2, a32 * inv3));
}

extern "C" void kernel_launch(void* const* d_in, const int* in_sizes, int n_in,
                              void* d_out, int out_size)
{
    const float* windows = (const float*)d_in[0];
    float* out = (float*)d_out;
    cudaFuncSetAttribute(wop_r15, cudaFuncAttributePreferredSharedMemoryCarveout, 100);
    // 8 b x 64 row-octets x 8 w-slabs = 4096 one-shot blocks
    wop_r15<<<4096, 128>>>(windows, out);
}